// round 1
// baseline (speedup 1.0000x reference)
#include <cuda_runtime.h>
#include <cstdint>

// Problem constants
#define B_TOTAL 4096
#define T_STEPS 1024
#define HID     64
#define GATES3  192            // 3*HID
#define NB      4              // batch elements per warp
#define WARPS   8              // warps per CTA
#define THREADS (WARPS * 32)
#define CTAS    (B_TOTAL / (NB * WARPS))   // 128

// packed fp32x2 FMA (Blackwell FFMA2 path — 2 MACs per lane-op)
__device__ __forceinline__ unsigned long long ffma2(unsigned long long a,
                                                    unsigned long long b,
                                                    unsigned long long c) {
    unsigned long long d;
    asm("fma.rn.f32x2 %0, %1, %2, %3;" : "=l"(d) : "l"(a), "l"(b), "l"(c));
    return d;
}
__device__ __forceinline__ float lo32(unsigned long long v) {
    return __uint_as_float((unsigned)v);
}
__device__ __forceinline__ float hi32(unsigned long long v) {
    return __uint_as_float((unsigned)(v >> 32));
}
__device__ __forceinline__ unsigned long long pack2(float lo, float hi) {
    return ((unsigned long long)__float_as_uint(hi) << 32) | __float_as_uint(lo);
}

__device__ __forceinline__ float sigm(float v) {
    float e = __expf(-v);
    return __fdividef(1.0f, 1.0f + e);
}
__device__ __forceinline__ float tanh_f(float v) {
    float e = __expf(2.0f * v);
    return 1.0f - __fdividef(2.0f, e + 1.0f);
}
__device__ __forceinline__ float lrelu(float v) {
    return v > 0.0f ? v : 0.01f * v;
}

__global__ __launch_bounds__(THREADS, 1)
void gru_fused(const float* __restrict__ x,
               const float* __restrict__ wih_g, const float* __restrict__ whh_g,
               const float* __restrict__ bih_g, const float* __restrict__ bhh_g,
               const float* __restrict__ w1, const float* __restrict__ b1,
               const float* __restrict__ w2, const float* __restrict__ b2,
               const float* __restrict__ w3, const float* __restrict__ b3,
               float* __restrict__ out)
{
    extern __shared__ float smem[];
    float* whh_s = smem;                          // [192][64] fp32, row-major
    float* h_s   = smem + GATES3 * HID;           // [WARPS][2][NB][HID]

    const int tid = threadIdx.x;
    const int w = tid >> 5;
    const int l = tid & 31;

    // Stage W_hh into smem (vectorized, coalesced)
    for (int i = tid; i < GATES3 * HID / 4; i += THREADS)
        ((float4*)whh_s)[i] = ((const float4*)whh_g)[i];

    // Zero both h buffers for this warp (h0 = 0)
    float* hw = h_s + w * (2 * NB * HID);
    for (int i = l; i < 2 * NB * HID; i += 32) hw[i] = 0.0f;

    __syncthreads();

    const int b0 = (blockIdx.x * WARPS + w) * NB;

    // Per-lane resident params. j = gate*2 + p  ->  row = gate*64 + l + 32*p
    float wih[6], bih[6], bhh[6];
    int rowbase[6];
#pragma unroll
    for (int g = 0; g < 3; ++g) {
#pragma unroll
        for (int p = 0; p < 2; ++p) {
            const int j = g * 2 + p;
            const int row = g * HID + l + 32 * p;
            rowbase[j] = row * HID;
            wih[j] = __ldg(&wih_g[row]);
            bih[j] = __ldg(&bih_g[row]);
            bhh[j] = __ldg(&bhh_g[row]);
        }
    }

    const float* xrow[NB];
#pragma unroll
    for (int b = 0; b < NB; ++b) xrow[b] = x + (size_t)(b0 + b) * T_STEPS;

    // ---------------- recurrence ----------------
    for (int t = 0; t < T_STEPS; ++t) {
        const float* hc = hw + (t & 1) * (NB * HID);
        float*       hn = hw + ((t + 1) & 1) * (NB * HID);

        // Packed accumulators: lo = even-k partial (+ b_hh), hi = odd-k partial
        unsigned long long acc[NB][6];
#pragma unroll
        for (int b = 0; b < NB; ++b)
#pragma unroll
            for (int j = 0; j < 6; ++j) acc[b][j] = pack2(bhh[j], 0.0f);

        // k in quads of 4; per-lane rotation (q+l)&15 => conflict-free LDS.128
#pragma unroll 4
        for (int q = 0; q < 16; ++q) {
            const int kq = ((q + l) & 15) * 4;

            ulonglong2 hv[NB];
#pragma unroll
            for (int b = 0; b < NB; ++b)
                hv[b] = *(const ulonglong2*)(hc + b * HID + kq);

#pragma unroll
            for (int j = 0; j < 6; ++j) {
                const ulonglong2 wv = *(const ulonglong2*)(whh_s + rowbase[j] + kq);
#pragma unroll
                for (int b = 0; b < NB; ++b) {
                    acc[b][j] = ffma2(wv.x, hv[b].x, acc[b][j]);
                    acc[b][j] = ffma2(wv.y, hv[b].y, acc[b][j]);
                }
            }
        }

        // Gates + state update (lane owns h indices l and l+32 per batch)
#pragma unroll
        for (int b = 0; b < NB; ++b) {
            const float xt = __ldg(&xrow[b][t]);
            float gh[6];
#pragma unroll
            for (int j = 0; j < 6; ++j) gh[j] = lo32(acc[b][j]) + hi32(acc[b][j]);

            const float r0v = sigm(fmaf(wih[0], xt, bih[0]) + gh[0]);
            const float r1v = sigm(fmaf(wih[1], xt, bih[1]) + gh[1]);
            const float z0v = sigm(fmaf(wih[2], xt, bih[2]) + gh[2]);
            const float z1v = sigm(fmaf(wih[3], xt, bih[3]) + gh[3]);
            const float n0v = tanh_f(fmaf(wih[4], xt, bih[4]) + r0v * gh[4]);
            const float n1v = tanh_f(fmaf(wih[5], xt, bih[5]) + r1v * gh[5]);

            const float h0 = hc[b * HID + l];
            const float h1 = hc[b * HID + l + 32];
            hn[b * HID + l]      = n0v + z0v * (h0 - n0v);
            hn[b * HID + l + 32] = n1v + z1v * (h1 - n1v);
        }
        __syncwarp();
    }

    // ---------------- MLP head: 64 -> 32 -> 16 -> 1 ----------------
    // T even => final h is in buffer 0; buffer 1 is free scratch.
    const float* hf  = hw;
    float*       scr = hw + NB * HID;

#pragma unroll
    for (int b = 0; b < NB; ++b) {
        const float* hb = hf + b * HID;

        // layer 1: each lane computes one of 32 outputs
        float a1 = __ldg(&b1[l]);
#pragma unroll 8
        for (int k = 0; k < HID; ++k)
            a1 = fmaf(__ldg(&w1[l * HID + k]), hb[k], a1);
        scr[l] = lrelu(a1);
        __syncwarp();

        // layer 2 (lanes 0..15) + layer 3 partials
        float part = 0.0f;
        if (l < 16) {
            float a2 = __ldg(&b2[l]);
#pragma unroll
            for (int k = 0; k < 32; ++k)
                a2 = fmaf(__ldg(&w2[l * 32 + k]), scr[k], a2);
            part = __ldg(&w3[l]) * lrelu(a2);
        }
#pragma unroll
        for (int off = 8; off; off >>= 1)
            part += __shfl_down_sync(0xffffffffu, part, off);
        if (l == 0) out[b0 + b] = part + __ldg(&b3[0]);
        __syncwarp();
    }
}

extern "C" void kernel_launch(void* const* d_in, const int* in_sizes, int n_in,
                              void* d_out, int out_size)
{
    const float* x     = (const float*)d_in[0];
    const float* wih   = (const float*)d_in[1];
    const float* whh   = (const float*)d_in[2];
    const float* bih   = (const float*)d_in[3];
    const float* bhh   = (const float*)d_in[4];
    const float* w1    = (const float*)d_in[5];
    const float* b1    = (const float*)d_in[6];
    const float* w2    = (const float*)d_in[7];
    const float* b2    = (const float*)d_in[8];
    const float* w3    = (const float*)d_in[9];
    const float* b3    = (const float*)d_in[10];
    float* out = (float*)d_out;

    const int smem_bytes = (GATES3 * HID + WARPS * 2 * NB * HID) * (int)sizeof(float); // 65536
    cudaFuncSetAttribute(gru_fused, cudaFuncAttributeMaxDynamicSharedMemorySize, smem_bytes);

    gru_fused<<<CTAS, THREADS, smem_bytes>>>(x, wih, whh, bih, bhh,
                                             w1, b1, w2, b2, w3, b3, out);
}